// round 1
// baseline (speedup 1.0000x reference)
#include <cuda_runtime.h>
#include <math.h>

#define BN 4096
#define DN 256
#define HN 768

// ---------------- device scratch (static, allocation-free) ----------------
__device__ float g_scal[8];        // 0,1,2 focal nums; 3 masksum; 4,5 ce nums; 6 recon ssum
__device__ float g_cnt[16];        // masked counts per (label*4+domain)
__device__ float g_G[2][256];      // ordered 16x16 Ksum histograms per feature set
__device__ float g_M[2][65536];    // raw 256x256 HSIC cross products per pair
__device__ float g_colsum[4][256]; // column sums of normalized feats
__device__ float g_nf[4][BN * DN]; // row-normalized c_v, s_v, c_t, s_t
__device__ float g_sq[2][BN];      // row squared norms of c_v, c_t
__device__ int   g_cls[BN];        // label*4+domain, or -1 if masked out

// ---------------- zero accumulators ----------------
__global__ void zero_kernel() {
    int i = blockIdx.x * blockDim.x + threadIdx.x;
    int stride = gridDim.x * blockDim.x;
    float* m = (float*)g_M;
    for (int e = i; e < 131072; e += stride) m[e] = 0.f;
    float* cs = (float*)g_colsum;
    for (int e = i; e < 1024; e += stride) cs[e] = 0.f;
    float* gg = (float*)g_G;
    for (int e = i; e < 512; e += stride) gg[e] = 0.f;
    if (i < 16) g_cnt[i] = 0.f;
    if (i < 8)  g_scal[i] = 0.f;
}

// ---------------- precompute: row sq norms, class ids, counts, masksum ----------------
__global__ void precompute_kernel(const float* __restrict__ cv, const float* __restrict__ ct,
                                  const int* __restrict__ lab, const int* __restrict__ dom,
                                  const unsigned char* __restrict__ mask) {
    int warp = (blockIdx.x * blockDim.x + threadIdx.x) >> 5;
    int lane = threadIdx.x & 31;
    if (warp >= BN) return;
    int r = warp;

    const float4* p = (const float4*)(cv + (size_t)r * DN);
    float s = 0.f;
    #pragma unroll
    for (int i = 0; i < 2; i++) {
        float4 v = p[lane + 32 * i];
        s += v.x * v.x + v.y * v.y + v.z * v.z + v.w * v.w;
    }
    #pragma unroll
    for (int o = 16; o; o >>= 1) s += __shfl_xor_sync(0xffffffffu, s, o);
    if (lane == 0) g_sq[0][r] = s;

    p = (const float4*)(ct + (size_t)r * DN);
    s = 0.f;
    #pragma unroll
    for (int i = 0; i < 2; i++) {
        float4 v = p[lane + 32 * i];
        s += v.x * v.x + v.y * v.y + v.z * v.z + v.w * v.w;
    }
    #pragma unroll
    for (int o = 16; o; o >>= 1) s += __shfl_xor_sync(0xffffffffu, s, o);
    if (lane == 0) g_sq[1][r] = s;

    if (lane == 0) {
        float w = mask[r] ? 1.f : 0.f;
        int c = lab[r] * 4 + dom[r];
        g_cls[r] = (w > 0.f) ? c : -1;
        if (w > 0.f) atomicAdd(&g_cnt[c], 1.f);
        atomicAdd(&g_scal[3], w);
    }
}

// ---------------- row-normalize the 4 HSIC feature matrices ----------------
__global__ void normalize_kernel(const float* __restrict__ in0, const float* __restrict__ in1,
                                 const float* __restrict__ in2, const float* __restrict__ in3) {
    int m = blockIdx.y;
    const float* src = (m == 0) ? in0 : (m == 1) ? in1 : (m == 2) ? in2 : in3;
    float* dst = g_nf[m];
    int warp = (blockIdx.x * blockDim.x + threadIdx.x) >> 5;
    int lane = threadIdx.x & 31;
    if (warp >= BN) return;

    const float4* p = (const float4*)(src + (size_t)warp * DN);
    float4 v0 = p[lane], v1 = p[lane + 32];
    float s = v0.x * v0.x + v0.y * v0.y + v0.z * v0.z + v0.w * v0.w
            + v1.x * v1.x + v1.y * v1.y + v1.z * v1.z + v1.w * v1.w;
    #pragma unroll
    for (int o = 16; o; o >>= 1) s += __shfl_xor_sync(0xffffffffu, s, o);
    float rn = 1.f / fmaxf(sqrtf(s), 1e-12f);

    float4* q = (float4*)(dst + (size_t)warp * DN);
    v0.x *= rn; v0.y *= rn; v0.z *= rn; v0.w *= rn;
    v1.x *= rn; v1.y *= rn; v1.z *= rn; v1.w *= rn;
    q[lane] = v0; q[lane + 32] = v1;
}

// ---------------- column sums of normalized feats (for rank-1 centering) ----------------
__global__ void colsum_kernel() {
    int m = blockIdx.y;
    int t = threadIdx.x;                 // 256 threads = 256 columns
    int r0 = blockIdx.x * 128;
    const float* src = g_nf[m];
    float s = 0.f;
    for (int r = 0; r < 128; r++) s += src[(size_t)(r0 + r) * DN + t];
    atomicAdd(&g_colsum[m][t], s);
}

// ---------------- focal (label-smoothed) loss numerator ----------------
__global__ void focal_kernel(const float* __restrict__ lg, const int* __restrict__ lb,
                             const unsigned char* __restrict__ mask, int nc, int slot) {
    int r = blockIdx.x * blockDim.x + threadIdx.x;
    float loss = 0.f;
    if (r < BN && mask[r]) {
        float x[6];
        float mx = -1e30f;
        for (int c = 0; c < nc; c++) { x[c] = lg[r * nc + c]; mx = fmaxf(mx, x[c]); }
        float se = 0.f, sx = 0.f;
        for (int c = 0; c < nc; c++) { se += expf(x[c] - mx); sx += x[c]; }
        float logZ = mx + logf(se);
        int t = lb[r];
        float ce = logZ - (0.9f * x[t] + (0.1f / (float)nc) * sx);
        float pt = expf(x[t] - logZ);
        float om = 1.f - pt;
        loss = ce * om * om;
    }
    __shared__ float red[256];
    red[threadIdx.x] = loss;
    __syncthreads();
    for (int s = 128; s; s >>= 1) { if (threadIdx.x < s) red[threadIdx.x] += red[threadIdx.x + s]; __syncthreads(); }
    if (threadIdx.x == 0) atomicAdd(&g_scal[slot], red[0]);
}

// ---------------- plain masked CE numerator (4 classes) ----------------
__global__ void ce_kernel(const float* __restrict__ lg, const int* __restrict__ lb,
                          const unsigned char* __restrict__ mask, int slot) {
    int r = blockIdx.x * blockDim.x + threadIdx.x;
    float loss = 0.f;
    if (r < BN && mask[r]) {
        float x0 = lg[r * 4 + 0], x1 = lg[r * 4 + 1], x2 = lg[r * 4 + 2], x3 = lg[r * 4 + 3];
        float mx = fmaxf(fmaxf(x0, x1), fmaxf(x2, x3));
        float se = expf(x0 - mx) + expf(x1 - mx) + expf(x2 - mx) + expf(x3 - mx);
        float logZ = mx + logf(se);
        int t = lb[r];
        float xt = (t == 0) ? x0 : (t == 1) ? x1 : (t == 2) ? x2 : x3;
        loss = logZ - xt;
    }
    __shared__ float red[256];
    red[threadIdx.x] = loss;
    __syncthreads();
    for (int s = 128; s; s >>= 1) { if (threadIdx.x < s) red[threadIdx.x] += red[threadIdx.x + s]; __syncthreads(); }
    if (threadIdx.x == 0) atomicAdd(&g_scal[slot], red[0]);
}

// ---------------- reconstruction MSE (summed; divided once at combine) ----------------
__global__ void recon_kernel(const float* __restrict__ a, const float* __restrict__ b,
                             const float* __restrict__ c, const float* __restrict__ d) {
    const int n4 = BN * HN / 4;
    float s = 0.f;
    for (int i = blockIdx.x * blockDim.x + threadIdx.x; i < n4; i += gridDim.x * blockDim.x) {
        float4 va = ((const float4*)a)[i], vb = ((const float4*)b)[i];
        float dx = va.x - vb.x, dy = va.y - vb.y, dz = va.z - vb.z, dw = va.w - vb.w;
        s += dx * dx + dy * dy + dz * dz + dw * dw;
        float4 vc = ((const float4*)c)[i], vd = ((const float4*)d)[i];
        dx = vc.x - vd.x; dy = vc.y - vd.y; dz = vc.z - vd.z; dw = vc.w - vd.w;
        s += dx * dx + dy * dy + dz * dz + dw * dw;
    }
    __shared__ float red[256];
    red[threadIdx.x] = s;
    __syncthreads();
    for (int st = 128; st; st >>= 1) { if (threadIdx.x < st) red[threadIdx.x] += red[threadIdx.x + st]; __syncthreads(); }
    if (threadIdx.x == 0) atomicAdd(&g_scal[6], red[0]);
}

// ---------------- HSIC GEMM: g_M[pair] += Cn^T * Sn  (256x256, k-split) ----------------
__global__ __launch_bounds__(256, 2) void hsic_gemm_kernel() {
    int pair = blockIdx.z;
    int tile = blockIdx.x;                 // 0..3 (2x2 tiles of 128)
    int tp = (tile >> 1) * 128, tq = (tile & 1) * 128;
    int k0 = blockIdx.y * 128;             // 32 k-splits
    const float* Cn = g_nf[2 * pair];
    const float* Sn = g_nf[2 * pair + 1];

    __shared__ float As[32][132];
    __shared__ float Bs[32][132];
    int tid = threadIdx.x, tx = tid & 15, ty = tid >> 4;

    float acc[8][8];
    #pragma unroll
    for (int u = 0; u < 8; u++)
        #pragma unroll
        for (int v = 0; v < 8; v++) acc[u][v] = 0.f;

    for (int kc = 0; kc < 128; kc += 32) {
        __syncthreads();
        #pragma unroll
        for (int pl = 0; pl < 4; pl++) {
            int f = tid + pl * 256;
            int kk = f >> 5;
            int cq = (f & 31) << 2;
            *(float4*)&As[kk][cq] = *(const float4*)(Cn + (size_t)(k0 + kc + kk) * DN + tp + cq);
            *(float4*)&Bs[kk][cq] = *(const float4*)(Sn + (size_t)(k0 + kc + kk) * DN + tq + cq);
        }
        __syncthreads();
        #pragma unroll 8
        for (int kk = 0; kk < 32; kk++) {
            float a[8], b[8];
            #pragma unroll
            for (int u = 0; u < 8; u++) a[u] = As[kk][ty + 16 * u];
            #pragma unroll
            for (int v = 0; v < 8; v++) b[v] = Bs[kk][tx + 16 * v];
            #pragma unroll
            for (int u = 0; u < 8; u++)
                #pragma unroll
                for (int v = 0; v < 8; v++) acc[u][v] = fmaf(a[u], b[v], acc[u][v]);
        }
    }
    #pragma unroll
    for (int u = 0; u < 8; u++) {
        int p = tp + ty + 16 * u;
        #pragma unroll
        for (int v = 0; v < 8; v++) {
            int q = tq + tx + 16 * v;
            atomicAdd(&g_M[pair][p * 256 + q], acc[u][v]);
        }
    }
}

// ---------------- Gram + multi-gamma RBF + 16x16 class histogram ----------------
__global__ __launch_bounds__(256, 2) void gram_kernel(const float* __restrict__ cv,
                                                      const float* __restrict__ ct) {
    const int T = BN / 128;                 // 32 tiles
    int set = blockIdx.y;
    const float* X = set ? ct : cv;

    int idx = blockIdx.x;                   // upper-triangle decode
    int ti = 0;
    while (idx >= T - ti) { idx -= T - ti; ti++; }
    int tj = ti + idx;
    int i0 = ti * 128, j0 = tj * 128;

    __shared__ float As[32][129];
    __shared__ float Bs[32][129];
    __shared__ float bins[256];
    __shared__ float sqi[128], sqj[128];
    __shared__ int   ci[128], cj[128];

    int tid = threadIdx.x;
    bins[tid] = 0.f;
    if (tid < 128) { sqi[tid] = g_sq[set][i0 + tid]; ci[tid] = g_cls[i0 + tid]; }
    else { int t = tid - 128; sqj[t] = g_sq[set][j0 + t]; cj[t] = g_cls[j0 + t]; }

    float acc[8][8];
    #pragma unroll
    for (int u = 0; u < 8; u++)
        #pragma unroll
        for (int v = 0; v < 8; v++) acc[u][v] = 0.f;

    int tx = tid & 15, ty = tid >> 4;

    for (int k0 = 0; k0 < DN; k0 += 32) {
        __syncthreads();
        #pragma unroll
        for (int pl = 0; pl < 4; pl++) {
            int f = tid + pl * 256;
            int row = f >> 3;
            int kq = (f & 7) << 2;
            float4 va = *(const float4*)(X + (size_t)(i0 + row) * DN + k0 + kq);
            As[kq + 0][row] = va.x; As[kq + 1][row] = va.y;
            As[kq + 2][row] = va.z; As[kq + 3][row] = va.w;
            float4 vb = *(const float4*)(X + (size_t)(j0 + row) * DN + k0 + kq);
            Bs[kq + 0][row] = vb.x; Bs[kq + 1][row] = vb.y;
            Bs[kq + 2][row] = vb.z; Bs[kq + 3][row] = vb.w;
        }
        __syncthreads();
        #pragma unroll 8
        for (int kk = 0; kk < 32; kk++) {
            float a[8], b[8];
            #pragma unroll
            for (int u = 0; u < 8; u++) a[u] = As[kk][ty + 16 * u];
            #pragma unroll
            for (int v = 0; v < 8; v++) b[v] = Bs[kk][tx + 16 * v];
            #pragma unroll
            for (int u = 0; u < 8; u++)
                #pragma unroll
                for (int v = 0; v < 8; v++) acc[u][v] = fmaf(a[u], b[v], acc[u][v]);
        }
    }

    bool diag = (ti == tj);
    #pragma unroll
    for (int u = 0; u < 8; u++) {
        int li = ty + 16 * u;
        int a_ = ci[li];
        float si = sqi[li];
        if (a_ < 0) continue;
        #pragma unroll
        for (int v = 0; v < 8; v++) {
            int lj = tx + 16 * v;
            int b_ = cj[lj];
            if (b_ < 0) continue;
            float Dv = si + sqj[lj] - 2.f * acc[u][v];
            float Kv = __expf(-0.01f * Dv) + __expf(-0.1f * Dv) + __expf(-1.0f * Dv)
                     + __expf(-10.f * Dv) + __expf(-100.f * Dv);
            atomicAdd(&bins[a_ * 16 + b_], Kv);
            if (!diag) atomicAdd(&bins[b_ * 16 + a_], Kv);
        }
    }
    __syncthreads();
    atomicAdd(&g_G[set][tid], bins[tid]);
}

// ---------------- combine everything into the scalar ----------------
__global__ void combine_kernel(float* __restrict__ out) {
    int tid = threadIdx.x;
    __shared__ float red[256];

    float p0 = 0.f, p1 = 0.f;
    const float invB = 1.f / (float)BN;
    for (int e = tid; e < 65536; e += 256) {
        int p = e >> 8, q = e & 255;
        float m0 = g_M[0][e] - g_colsum[0][p] * g_colsum[1][q] * invB;
        p0 += m0 * m0;
        float m1 = g_M[1][e] - g_colsum[2][p] * g_colsum[3][q] * invB;
        p1 += m1 * m1;
    }
    red[tid] = p0; __syncthreads();
    for (int s = 128; s; s >>= 1) { if (tid < s) red[tid] += red[tid + s]; __syncthreads(); }
    float hs0 = 0.f;
    if (tid == 0) hs0 = red[0];
    __syncthreads();
    red[tid] = p1; __syncthreads();
    for (int s = 128; s; s >>= 1) { if (tid < s) red[tid] += red[tid + s]; __syncthreads(); }

    if (tid == 0) {
        float hs1 = red[0];
        float denomH = 4095.f * 4095.f;
        float hsic_sum = (hs0 + hs1) / denomH;

        float mmd[2];
        for (int s = 0; s < 2; s++) {
            float loss = 0.f, count = 0.f;
            for (int lab = 0; lab < 4; lab++)
                for (int d1 = 0; d1 < 4; d1++) {
                    int a = lab * 4 + d1;
                    float n1 = g_cnt[a];
                    for (int d2 = d1 + 1; d2 < 4; d2++) {
                        int b = lab * 4 + d2;
                        float n2 = g_cnt[b];
                        if (n1 > 1.f && n2 > 1.f) {
                            float ga = g_G[s][a * 16 + a];
                            float gb = g_G[s][b * 16 + b];
                            float gab = g_G[s][a * 16 + b];
                            float m1m = fmaxf(n1, 1.f), m2m = fmaxf(n2, 1.f);
                            float term = ga / (m1m * m1m) + gb / (m2m * m2m)
                                       - 2.f * gab / fmaxf(n1 * n2, 1.f);
                            loss += term;
                            count += 1.f;
                        }
                    }
                }
            mmd[s] = loss / fmaxf(count, 1.f);
        }

        float msum = fmaxf(g_scal[3], 1.f);
        float total = 0.4f * g_scal[0] / msum + 0.3f * g_scal[1] / msum + 0.3f * g_scal[2] / msum;
        total += 0.1f * (g_scal[4] / msum + g_scal[5] / msum + mmd[0] + mmd[1]);
        total += 0.1f * hsic_sum;
        total += g_scal[6] / (float)(BN * HN);
        out[0] = total;
    }
}

// ---------------- launch ----------------
extern "C" void kernel_launch(void* const* d_in, const int* in_sizes, int n_in,
                              void* d_out, int out_size) {
    (void)in_sizes; (void)n_in; (void)out_size;
    const float* logits1 = (const float*)d_in[0];
    const int*   labels1 = (const int*)d_in[1];
    const float* logits2 = (const float*)d_in[2];
    const int*   labels2 = (const int*)d_in[3];
    const float* logits3 = (const float*)d_in[4];
    const int*   labels3 = (const int*)d_in[5];
    const float* c_v  = (const float*)d_in[6];
    const float* s_v  = (const float*)d_in[7];
    const float* c_t  = (const float*)d_in[8];
    const float* s_t  = (const float*)d_in[9];
    const float* v_sv = (const float*)d_in[10];
    const float* v_st = (const float*)d_in[11];
    const int*   dom  = (const int*)d_in[12];
    const unsigned char* mask = (const unsigned char*)d_in[13];
    const float* hir = (const float*)d_in[14];
    const float* hio = (const float*)d_in[15];
    const float* htr = (const float*)d_in[16];
    const float* hto = (const float*)d_in[17];

    zero_kernel<<<148, 256>>>();
    precompute_kernel<<<512, 256>>>(c_v, c_t, labels1, dom, mask);
    normalize_kernel<<<dim3(512, 4), 256>>>(c_v, s_v, c_t, s_t);
    colsum_kernel<<<dim3(32, 4), 256>>>();
    focal_kernel<<<16, 256>>>(logits1, labels1, mask, 4, 0);
    focal_kernel<<<16, 256>>>(logits2, labels2, mask, 6, 1);
    focal_kernel<<<16, 256>>>(logits3, labels3, mask, 3, 2);
    ce_kernel<<<16, 256>>>(v_sv, dom, mask, 4);
    ce_kernel<<<16, 256>>>(v_st, dom, mask, 5);
    recon_kernel<<<256, 256>>>(hir, hio, htr, hto);
    hsic_gemm_kernel<<<dim3(4, 32, 2), 256>>>();
    gram_kernel<<<dim3(528, 2), 256>>>(c_v, c_t);
    combine_kernel<<<1, 256>>>((float*)d_out);
}

// round 3
// speedup vs baseline: 1.8537x; 1.8537x over previous
#include <cuda_runtime.h>
#include <cuda_bf16.h>
#include <math.h>

#define BN 4096
#define DN 256
#define HN 768

// ---------------- device scratch (static, allocation-free) ----------------
__device__ float g_scal[8];        // 0,1,2 focal nums; 3 masksum; 4,5 ce nums; 6 recon ssum
__device__ float g_cnt[16];        // masked counts per (label*4+domain)
__device__ float g_G[2][256];      // UNORDERED (single-counted) 16x16 Ksum histograms
__device__ float g_M[2][65536];    // raw 256x256 HSIC cross products per pair
__device__ float g_colsum[4][256]; // column sums of normalized feats
__device__ float g_nf[4][BN * DN]; // row-normalized c_v, s_v, c_t, s_t
__device__ float g_sq[2][BN];      // row squared norms of bf16(c_v), bf16(c_t)
__device__ int   g_cls[BN];        // label*4+domain, or -1 if masked out
__device__ __nv_bfloat16 g_bf[2][BN * DN];  // bf16 copies of c_v, c_t

__device__ __forceinline__ unsigned smem_u32(const void* p) {
    return (unsigned)__cvta_generic_to_shared(p);
}

// ---------------- zero accumulators ----------------
__global__ void zero_kernel() {
    int i = blockIdx.x * blockDim.x + threadIdx.x;
    int stride = gridDim.x * blockDim.x;
    float* m = (float*)g_M;
    for (int e = i; e < 131072; e += stride) m[e] = 0.f;
    float* cs = (float*)g_colsum;
    for (int e = i; e < 1024; e += stride) cs[e] = 0.f;
    float* gg = (float*)g_G;
    for (int e = i; e < 512; e += stride) gg[e] = 0.f;
    if (i < 16) g_cnt[i] = 0.f;
    if (i < 8)  g_scal[i] = 0.f;
}

// ---------------- precompute: bf16 convert + bf16 row sq norms, class ids ----------------
__global__ void precompute_kernel(const float* __restrict__ cv, const float* __restrict__ ct,
                                  const int* __restrict__ lab, const int* __restrict__ dom,
                                  const unsigned char* __restrict__ mask) {
    int warp = (blockIdx.x * blockDim.x + threadIdx.x) >> 5;
    int lane = threadIdx.x & 31;
    if (warp >= BN) return;
    int r = warp;

    #pragma unroll
    for (int set = 0; set < 2; set++) {
        const float* src = set ? ct : cv;
        const float4* p = (const float4*)(src + (size_t)r * DN);
        float4 v0 = p[lane * 2], v1 = p[lane * 2 + 1];
        __nv_bfloat16 t[8];
        t[0] = __float2bfloat16(v0.x); t[1] = __float2bfloat16(v0.y);
        t[2] = __float2bfloat16(v0.z); t[3] = __float2bfloat16(v0.w);
        t[4] = __float2bfloat16(v1.x); t[5] = __float2bfloat16(v1.y);
        t[6] = __float2bfloat16(v1.z); t[7] = __float2bfloat16(v1.w);
        float s = 0.f;
        #pragma unroll
        for (int i = 0; i < 8; i++) { float f = __bfloat162float(t[i]); s += f * f; }
        #pragma unroll
        for (int o = 16; o; o >>= 1) s += __shfl_xor_sync(0xffffffffu, s, o);
        if (lane == 0) g_sq[set][r] = s;
        *(uint4*)(g_bf[set] + (size_t)r * DN + lane * 8) = *(uint4*)t;
    }

    if (lane == 0) {
        float w = mask[r] ? 1.f : 0.f;
        int c = lab[r] * 4 + dom[r];
        g_cls[r] = (w > 0.f) ? c : -1;
        if (w > 0.f) atomicAdd(&g_cnt[c], 1.f);
        atomicAdd(&g_scal[3], w);
    }
}

// ---------------- row-normalize the 4 HSIC feature matrices ----------------
__global__ void normalize_kernel(const float* __restrict__ in0, const float* __restrict__ in1,
                                 const float* __restrict__ in2, const float* __restrict__ in3) {
    int m = blockIdx.y;
    const float* src = (m == 0) ? in0 : (m == 1) ? in1 : (m == 2) ? in2 : in3;
    float* dst = g_nf[m];
    int warp = (blockIdx.x * blockDim.x + threadIdx.x) >> 5;
    int lane = threadIdx.x & 31;
    if (warp >= BN) return;

    const float4* p = (const float4*)(src + (size_t)warp * DN);
    float4 v0 = p[lane], v1 = p[lane + 32];
    float s = v0.x * v0.x + v0.y * v0.y + v0.z * v0.z + v0.w * v0.w
            + v1.x * v1.x + v1.y * v1.y + v1.z * v1.z + v1.w * v1.w;
    #pragma unroll
    for (int o = 16; o; o >>= 1) s += __shfl_xor_sync(0xffffffffu, s, o);
    float rn = 1.f / fmaxf(sqrtf(s), 1e-12f);

    float4* q = (float4*)(dst + (size_t)warp * DN);
    v0.x *= rn; v0.y *= rn; v0.z *= rn; v0.w *= rn;
    v1.x *= rn; v1.y *= rn; v1.z *= rn; v1.w *= rn;
    q[lane] = v0; q[lane + 32] = v1;
}

// ---------------- column sums of normalized feats (rank-1 centering) ----------------
__global__ void colsum_kernel() {
    int m = blockIdx.y;
    int t = threadIdx.x;                 // 256 threads = 256 columns
    int r0 = blockIdx.x * 16;            // 256 blocks x 16 rows
    const float* src = g_nf[m];
    float s = 0.f;
    #pragma unroll
    for (int r = 0; r < 16; r++) s += src[(size_t)(r0 + r) * DN + t];
    atomicAdd(&g_colsum[m][t], s);
}

// ---------------- focal (label-smoothed) loss numerator ----------------
__global__ void focal_kernel(const float* __restrict__ lg, const int* __restrict__ lb,
                             const unsigned char* __restrict__ mask, int nc, int slot) {
    int r = blockIdx.x * blockDim.x + threadIdx.x;
    float loss = 0.f;
    if (r < BN && mask[r]) {
        float x[6];
        float mx = -1e30f;
        for (int c = 0; c < nc; c++) { x[c] = lg[r * nc + c]; mx = fmaxf(mx, x[c]); }
        float se = 0.f, sx = 0.f;
        for (int c = 0; c < nc; c++) { se += expf(x[c] - mx); sx += x[c]; }
        float logZ = mx + logf(se);
        int t = lb[r];
        float ce = logZ - (0.9f * x[t] + (0.1f / (float)nc) * sx);
        float pt = expf(x[t] - logZ);
        float om = 1.f - pt;
        loss = ce * om * om;
    }
    __shared__ float red[256];
    red[threadIdx.x] = loss;
    __syncthreads();
    for (int s = 128; s; s >>= 1) { if (threadIdx.x < s) red[threadIdx.x] += red[threadIdx.x + s]; __syncthreads(); }
    if (threadIdx.x == 0) atomicAdd(&g_scal[slot], red[0]);
}

// ---------------- plain masked CE numerator (4 classes) ----------------
__global__ void ce_kernel(const float* __restrict__ lg, const int* __restrict__ lb,
                          const unsigned char* __restrict__ mask, int slot) {
    int r = blockIdx.x * blockDim.x + threadIdx.x;
    float loss = 0.f;
    if (r < BN && mask[r]) {
        float x0 = lg[r * 4 + 0], x1 = lg[r * 4 + 1], x2 = lg[r * 4 + 2], x3 = lg[r * 4 + 3];
        float mx = fmaxf(fmaxf(x0, x1), fmaxf(x2, x3));
        float se = expf(x0 - mx) + expf(x1 - mx) + expf(x2 - mx) + expf(x3 - mx);
        float logZ = mx + logf(se);
        int t = lb[r];
        float xt = (t == 0) ? x0 : (t == 1) ? x1 : (t == 2) ? x2 : x3;
        loss = logZ - xt;
    }
    __shared__ float red[256];
    red[threadIdx.x] = loss;
    __syncthreads();
    for (int s = 128; s; s >>= 1) { if (threadIdx.x < s) red[threadIdx.x] += red[threadIdx.x + s]; __syncthreads(); }
    if (threadIdx.x == 0) atomicAdd(&g_scal[slot], red[0]);
}

// ---------------- reconstruction MSE (summed) ----------------
__global__ void recon_kernel(const float* __restrict__ a, const float* __restrict__ b,
                             const float* __restrict__ c, const float* __restrict__ d) {
    const int n4 = BN * HN / 4;
    float s = 0.f;
    for (int i = blockIdx.x * blockDim.x + threadIdx.x; i < n4; i += gridDim.x * blockDim.x) {
        float4 va = ((const float4*)a)[i], vb = ((const float4*)b)[i];
        float dx = va.x - vb.x, dy = va.y - vb.y, dz = va.z - vb.z, dw = va.w - vb.w;
        s += dx * dx + dy * dy + dz * dz + dw * dw;
        float4 vc = ((const float4*)c)[i], vd = ((const float4*)d)[i];
        dx = vc.x - vd.x; dy = vc.y - vd.y; dz = vc.z - vd.z; dw = vc.w - vd.w;
        s += dx * dx + dy * dy + dz * dz + dw * dw;
    }
    __shared__ float red[256];
    red[threadIdx.x] = s;
    __syncthreads();
    for (int st = 128; st; st >>= 1) { if (threadIdx.x < st) red[threadIdx.x] += red[threadIdx.x + st]; __syncthreads(); }
    if (threadIdx.x == 0) atomicAdd(&g_scal[6], red[0]);
}

// ---------------- HSIC GEMM: g_M[pair] += Cn^T * Sn  (256x256, k-split) ----------------
__global__ __launch_bounds__(256, 2) void hsic_gemm_kernel() {
    int pair = blockIdx.z;
    int tile = blockIdx.x;
    int tp = (tile >> 1) * 128, tq = (tile & 1) * 128;
    int k0 = blockIdx.y * 128;
    const float* Cn = g_nf[2 * pair];
    const float* Sn = g_nf[2 * pair + 1];

    __shared__ float As[32][132];
    __shared__ float Bs[32][132];
    int tid = threadIdx.x, tx = tid & 15, ty = tid >> 4;

    float acc[8][8];
    #pragma unroll
    for (int u = 0; u < 8; u++)
        #pragma unroll
        for (int v = 0; v < 8; v++) acc[u][v] = 0.f;

    for (int kc = 0; kc < 128; kc += 32) {
        __syncthreads();
        #pragma unroll
        for (int pl = 0; pl < 4; pl++) {
            int f = tid + pl * 256;
            int kk = f >> 5;
            int cq = (f & 31) << 2;
            *(float4*)&As[kk][cq] = *(const float4*)(Cn + (size_t)(k0 + kc + kk) * DN + tp + cq);
            *(float4*)&Bs[kk][cq] = *(const float4*)(Sn + (size_t)(k0 + kc + kk) * DN + tq + cq);
        }
        __syncthreads();
        #pragma unroll 8
        for (int kk = 0; kk < 32; kk++) {
            float a[8], b[8];
            #pragma unroll
            for (int u = 0; u < 8; u++) a[u] = As[kk][ty + 16 * u];
            #pragma unroll
            for (int v = 0; v < 8; v++) b[v] = Bs[kk][tx + 16 * v];
            #pragma unroll
            for (int u = 0; u < 8; u++)
                #pragma unroll
                for (int v = 0; v < 8; v++) acc[u][v] = fmaf(a[u], b[v], acc[u][v]);
        }
    }
    #pragma unroll
    for (int u = 0; u < 8; u++) {
        int p = tp + ty + 16 * u;
        #pragma unroll
        for (int v = 0; v < 8; v++) {
            int q = tq + tx + 16 * v;
            atomicAdd(&g_M[pair][p * 256 + q], acc[u][v]);
        }
    }
}

// ---------------- bf16 tensor-core Gram + multi-gamma RBF + 16x16 histogram ----------------
// 128x128 tile per block, upper triangle; mma.sync m16n8k16 bf16->f32.
#define PITCH 72   // bf16 elems per smem row (144 B, conflict-free for ldmatrix phases)
#define KC 64

__global__ __launch_bounds__(256) void gram_mma_kernel() {
    const int T = BN / 128;                 // 32
    int set = blockIdx.y;
    const __nv_bfloat16* X = g_bf[set];

    int idx = blockIdx.x;                   // upper-triangle decode
    int ti = 0;
    while (idx >= T - ti) { idx -= T - ti; ti++; }
    int tj = ti + idx;
    int i0 = ti * 128, j0 = tj * 128;
    bool diag = (ti == tj);

    __shared__ __nv_bfloat16 As[128 * PITCH];
    __shared__ __nv_bfloat16 Bs[128 * PITCH];
    __shared__ float bins[8][256];
    __shared__ float sqi[128], sqj[128];
    __shared__ int   ci_s[128], cj_s[128];

    int tid = threadIdx.x;
    int wid = tid >> 5, lane = tid & 31;
    for (int b = tid; b < 2048; b += 256) ((float*)bins)[b] = 0.f;
    if (tid < 128) { sqi[tid] = g_sq[set][i0 + tid]; ci_s[tid] = g_cls[i0 + tid]; }
    else { int t = tid - 128; sqj[t] = g_sq[set][j0 + t]; cj_s[t] = g_cls[j0 + t]; }

    int wm = wid >> 2, wn = wid & 3;        // warp tile 64x32 at (wm*64, wn*32)

    float acc[4][4][4];                     // [mi][ni][reg]
    #pragma unroll
    for (int mi = 0; mi < 4; mi++)
        #pragma unroll
        for (int ni = 0; ni < 4; ni++)
            #pragma unroll
            for (int r = 0; r < 4; r++) acc[mi][ni][r] = 0.f;

    unsigned as_base = smem_u32(As);
    unsigned bs_base = smem_u32(Bs);

    for (int kc = 0; kc < DN; kc += KC) {
        __syncthreads();
        #pragma unroll
        for (int p = 0; p < 4; p++) {
            int v = tid + p * 256;
            int row = v >> 3, c8 = v & 7;
            uint4 da = *(const uint4*)(X + (size_t)(i0 + row) * DN + kc + c8 * 8);
            *(uint4*)(As + row * PITCH + c8 * 8) = da;
            uint4 db = *(const uint4*)(X + (size_t)(j0 + row) * DN + kc + c8 * 8);
            *(uint4*)(Bs + row * PITCH + c8 * 8) = db;
        }
        __syncthreads();
        #pragma unroll
        for (int ks = 0; ks < KC; ks += 16) {
            unsigned a[4][4], b[4][2];
            #pragma unroll
            for (int mi = 0; mi < 4; mi++) {
                int row = wm * 64 + mi * 16 + (lane & 15);
                unsigned addr = as_base + (row * PITCH + ks + (lane >> 4) * 8) * 2;
                asm volatile("ldmatrix.sync.aligned.m8n8.x4.shared.b16 {%0,%1,%2,%3}, [%4];"
                             : "=r"(a[mi][0]), "=r"(a[mi][1]), "=r"(a[mi][2]), "=r"(a[mi][3])
                             : "r"(addr));
            }
            #pragma unroll
            for (int p = 0; p < 2; p++) {
                int g = lane >> 3, r = lane & 7;
                int row = wn * 32 + p * 16 + (g >> 1) * 8 + r;
                unsigned addr = bs_base + (row * PITCH + ks + (g & 1) * 8) * 2;
                unsigned r0, r1, r2, r3;
                asm volatile("ldmatrix.sync.aligned.m8n8.x4.shared.b16 {%0,%1,%2,%3}, [%4];"
                             : "=r"(r0), "=r"(r1), "=r"(r2), "=r"(r3) : "r"(addr));
                b[p * 2][0] = r0;  b[p * 2][1] = r1;
                b[p * 2 + 1][0] = r2;  b[p * 2 + 1][1] = r3;
            }
            #pragma unroll
            for (int mi = 0; mi < 4; mi++)
                #pragma unroll
                for (int ni = 0; ni < 4; ni++) {
                    asm volatile(
                        "mma.sync.aligned.m16n8k16.row.col.f32.bf16.bf16.f32 "
                        "{%0,%1,%2,%3}, {%4,%5,%6,%7}, {%8,%9}, {%0,%1,%2,%3};"
                        : "+f"(acc[mi][ni][0]), "+f"(acc[mi][ni][1]),
                          "+f"(acc[mi][ni][2]), "+f"(acc[mi][ni][3])
                        : "r"(a[mi][0]), "r"(a[mi][1]), "r"(a[mi][2]), "r"(a[mi][3]),
                          "r"(b[ni][0]), "r"(b[ni][1]));
                }
        }
    }

    // epilogue: D -> multi-gamma RBF -> class histogram (single-counted)
    #pragma unroll
    for (int mi = 0; mi < 4; mi++) {
        int rbase = wm * 64 + mi * 16 + (lane >> 2);
        #pragma unroll
        for (int ni = 0; ni < 4; ni++) {
            int cbase = wn * 32 + ni * 8 + (lane & 3) * 2;
            #pragma unroll
            for (int rr = 0; rr < 2; rr++) {
                int il = rbase + rr * 8;
                int aCls = ci_s[il];
                if (aCls < 0) continue;
                float si = sqi[il];
                #pragma unroll
                for (int cc = 0; cc < 2; cc++) {
                    int jl = cbase + cc;
                    int bCls = cj_s[jl];
                    if (bCls < 0) continue;
                    if (diag) {
                        if (jl < il) continue;
                        if (jl == il) { atomicAdd(&bins[wid][aCls * 17], 2.5f); continue; }
                    }
                    float dot = acc[mi][ni][rr * 2 + cc];
                    float D = si + sqj[jl] - 2.f * dot;
                    float Kv = __expf(-0.01f * D);
                    if (D < 340.f) {
                        Kv += __expf(-0.1f * D) + __expf(-D)
                            + __expf(-10.f * D) + __expf(-100.f * D);
                    }
                    atomicAdd(&bins[wid][aCls * 16 + bCls], Kv);
                }
            }
        }
    }
    __syncthreads();
    {
        float s = 0.f;
        #pragma unroll
        for (int w = 0; w < 8; w++) s += bins[w][tid];
        atomicAdd(&g_G[set][tid], s);
    }
}

// ---------------- combine everything into the scalar ----------------
__global__ void combine_kernel(float* __restrict__ out) {
    int tid = threadIdx.x;
    __shared__ float red[256];

    float p0 = 0.f, p1 = 0.f;
    const float invB = 1.f / (float)BN;
    for (int e = tid; e < 65536; e += 256) {
        int p = e >> 8, q = e & 255;
        float m0 = g_M[0][e] - g_colsum[0][p] * g_colsum[1][q] * invB;
        p0 += m0 * m0;
        float m1 = g_M[1][e] - g_colsum[2][p] * g_colsum[3][q] * invB;
        p1 += m1 * m1;
    }
    red[tid] = p0; __syncthreads();
    for (int s = 128; s; s >>= 1) { if (tid < s) red[tid] += red[tid + s]; __syncthreads(); }
    float hs0 = 0.f;
    if (tid == 0) hs0 = red[0];
    __syncthreads();
    red[tid] = p1; __syncthreads();
    for (int s = 128; s; s >>= 1) { if (tid < s) red[tid] += red[tid + s]; __syncthreads(); }

    if (tid == 0) {
        float hs1 = red[0];
        float denomH = 4095.f * 4095.f;
        float hsic_sum = (hs0 + hs1) / denomH;

        float mmd[2];
        for (int s = 0; s < 2; s++) {
            float loss = 0.f, count = 0.f;
            for (int lab = 0; lab < 4; lab++)
                for (int d1 = 0; d1 < 4; d1++) {
                    int a = lab * 4 + d1;
                    float n1 = g_cnt[a];
                    for (int d2 = d1 + 1; d2 < 4; d2++) {
                        int b = lab * 4 + d2;
                        float n2 = g_cnt[b];
                        if (n1 > 1.f && n2 > 1.f) {
                            float ga = 2.f * g_G[s][a * 16 + a];
                            float gb = 2.f * g_G[s][b * 16 + b];
                            float gab = g_G[s][a * 16 + b] + g_G[s][b * 16 + a];
                            float m1m = fmaxf(n1, 1.f), m2m = fmaxf(n2, 1.f);
                            float term = ga / (m1m * m1m) + gb / (m2m * m2m)
                                       - 2.f * gab / fmaxf(n1 * n2, 1.f);
                            loss += term;
                            count += 1.f;
                        }
                    }
                }
            mmd[s] = loss / fmaxf(count, 1.f);
        }

        float msum = fmaxf(g_scal[3], 1.f);
        float total = 0.4f * g_scal[0] / msum + 0.3f * g_scal[1] / msum + 0.3f * g_scal[2] / msum;
        total += 0.1f * (g_scal[4] / msum + g_scal[5] / msum + mmd[0] + mmd[1]);
        total += 0.1f * hsic_sum;
        total += g_scal[6] / (float)(BN * HN);
        out[0] = total;
    }
}

// ---------------- launch ----------------
extern "C" void kernel_launch(void* const* d_in, const int* in_sizes, int n_in,
                              void* d_out, int out_size) {
    (void)in_sizes; (void)n_in; (void)out_size;
    const float* logits1 = (const float*)d_in[0];
    const int*   labels1 = (const int*)d_in[1];
    const float* logits2 = (const float*)d_in[2];
    const int*   labels2 = (const int*)d_in[3];
    const float* logits3 = (const float*)d_in[4];
    const int*   labels3 = (const int*)d_in[5];
    const float* c_v  = (const float*)d_in[6];
    const float* s_v  = (const float*)d_in[7];
    const float* c_t  = (const float*)d_in[8];
    const float* s_t  = (const float*)d_in[9];
    const float* v_sv = (const float*)d_in[10];
    const float* v_st = (const float*)d_in[11];
    const int*   dom  = (const int*)d_in[12];
    const unsigned char* mask = (const unsigned char*)d_in[13];
    const float* hir = (const float*)d_in[14];
    const float* hio = (const float*)d_in[15];
    const float* htr = (const float*)d_in[16];
    const float* hto = (const float*)d_in[17];

    zero_kernel<<<148, 256>>>();
    precompute_kernel<<<512, 256>>>(c_v, c_t, labels1, dom, mask);
    normalize_kernel<<<dim3(512, 4), 256>>>(c_v, s_v, c_t, s_t);
    colsum_kernel<<<dim3(256, 4), 256>>>();
    focal_kernel<<<16, 256>>>(logits1, labels1, mask, 4, 0);
    focal_kernel<<<16, 256>>>(logits2, labels2, mask, 6, 1);
    focal_kernel<<<16, 256>>>(logits3, labels3, mask, 3, 2);
    ce_kernel<<<16, 256>>>(v_sv, dom, mask, 4);
    ce_kernel<<<16, 256>>>(v_st, dom, mask, 5);
    recon_kernel<<<256, 256>>>(hir, hio, htr, hto);
    hsic_gemm_kernel<<<dim3(4, 32, 2), 256>>>();
    gram_mma_kernel<<<dim3(528, 2), 256>>>();
    combine_kernel<<<1, 256>>>((float*)d_out);
}

// round 5
// speedup vs baseline: 2.8652x; 1.5457x over previous
#include <cuda_runtime.h>
#include <cuda_bf16.h>
#include <math.h>

#define BN 4096
#define DN 256
#define HN 768

// ---------------- device scratch (static, allocation-free) ----------------
__device__ float g_scal[8];        // 0,1,2 focal; 3 masksum; 4,5 ce; 6 recon; 7 hsic frob
__device__ float g_cnt[16];        // masked counts per (label*4+domain)
__device__ float g_G[2][256];      // single-counted 16x16 Ksum histograms
__device__ float g_Ms[2][16][65536]; // per-k-split HSIC cross products (no zero/atomics)
__device__ float g_colsum[4][256]; // column sums of normalized bf16 feats
__device__ float g_rn[4][BN];      // 1/row-norm of c_v, s_v, c_t, s_t
__device__ __nv_bfloat16 g_nfT[4][DN * BN]; // normalized, transposed (p-major, i contig)
__device__ float g_sq[2][BN];      // row squared norms of bf16(c_v), bf16(c_t)
__device__ int   g_cls[BN];        // label*4+domain, or -1 if masked out
__device__ __nv_bfloat16 g_bf[2][BN * DN];  // bf16 copies of c_v, c_t

__device__ __forceinline__ unsigned smem_u32(const void* p) {
    return (unsigned)__cvta_generic_to_shared(p);
}

// ---------------- zero the small accumulators ----------------
__global__ void zero_kernel() {
    int i = threadIdx.x;
    float* gg = (float*)g_G;
    for (int e = i; e < 512; e += 256) gg[e] = 0.f;
    if (i < 16) g_cnt[i] = 0.f;
    if (i < 8)  g_scal[i] = 0.f;
}

// ---------------- precompute: bf16 convert + bf16 row sq norms, class ids ----------------
__global__ void precompute_kernel(const float* __restrict__ cv, const float* __restrict__ ct,
                                  const int* __restrict__ lab, const int* __restrict__ dom,
                                  const unsigned char* __restrict__ mask) {
    int warp = (blockIdx.x * blockDim.x + threadIdx.x) >> 5;
    int lane = threadIdx.x & 31;
    if (warp >= BN) return;
    int r = warp;

    #pragma unroll
    for (int set = 0; set < 2; set++) {
        const float* src = set ? ct : cv;
        const float4* p = (const float4*)(src + (size_t)r * DN);
        float4 v0 = p[lane * 2], v1 = p[lane * 2 + 1];
        __nv_bfloat16 t[8];
        t[0] = __float2bfloat16(v0.x); t[1] = __float2bfloat16(v0.y);
        t[2] = __float2bfloat16(v0.z); t[3] = __float2bfloat16(v0.w);
        t[4] = __float2bfloat16(v1.x); t[5] = __float2bfloat16(v1.y);
        t[6] = __float2bfloat16(v1.z); t[7] = __float2bfloat16(v1.w);
        float s = 0.f;
        #pragma unroll
        for (int i = 0; i < 8; i++) { float f = __bfloat162float(t[i]); s += f * f; }
        #pragma unroll
        for (int o = 16; o; o >>= 1) s += __shfl_xor_sync(0xffffffffu, s, o);
        if (lane == 0) g_sq[set][r] = s;
        *(uint4*)(g_bf[set] + (size_t)r * DN + lane * 8) = *(uint4*)t;
    }

    if (lane == 0) {
        float w = mask[r] ? 1.f : 0.f;
        int c = lab[r] * 4 + dom[r];
        g_cls[r] = (w > 0.f) ? c : -1;
        if (w > 0.f) atomicAdd(&g_cnt[c], 1.f);
        atomicAdd(&g_scal[3], w);
    }
}

// ---------------- row norms of the 4 HSIC feature matrices ----------------
__global__ void norms_kernel(const float* __restrict__ in0, const float* __restrict__ in1,
                             const float* __restrict__ in2, const float* __restrict__ in3) {
    int m = blockIdx.y;
    const float* src = (m == 0) ? in0 : (m == 1) ? in1 : (m == 2) ? in2 : in3;
    int warp = (blockIdx.x * blockDim.x + threadIdx.x) >> 5;
    int lane = threadIdx.x & 31;
    if (warp >= BN) return;

    const float4* p = (const float4*)(src + (size_t)warp * DN);
    float4 v0 = p[lane], v1 = p[lane + 32];
    float s = v0.x * v0.x + v0.y * v0.y + v0.z * v0.z + v0.w * v0.w
            + v1.x * v1.x + v1.y * v1.y + v1.z * v1.z + v1.w * v1.w;
    #pragma unroll
    for (int o = 16; o; o >>= 1) s += __shfl_xor_sync(0xffffffffu, s, o);
    if (lane == 0) g_rn[m][warp] = 1.f / fmaxf(sqrtf(s), 1e-12f);
}

// ---------------- normalize + transpose to bf16 (p-major, i contiguous) ----------------
__global__ void transposeN_kernel(const float* __restrict__ in0, const float* __restrict__ in1,
                                  const float* __restrict__ in2, const float* __restrict__ in3) {
    int m = blockIdx.z;
    const float* src = (m == 0) ? in0 : (m == 1) ? in1 : (m == 2) ? in2 : in3;
    __nv_bfloat16* dst = g_nfT[m];
    int i0 = blockIdx.x * 64, p0 = blockIdx.y * 64;

    __shared__ __nv_bfloat16 smT[64][88];   // [p_local][i_local], pitch 88 (176B, 16B-mult)
    __shared__ float rns[64];
    int tid = threadIdx.x;
    if (tid < 64) rns[tid] = g_rn[m][i0 + tid];
    __syncthreads();

    #pragma unroll
    for (int s = tid; s < 1024; s += 256) {
        int r = s >> 4, c4 = (s & 15) * 4;
        float4 v = *(const float4*)(src + (size_t)(i0 + r) * DN + p0 + c4);
        float rn = rns[r];
        smT[c4 + 0][r] = __float2bfloat16(v.x * rn);
        smT[c4 + 1][r] = __float2bfloat16(v.y * rn);
        smT[c4 + 2][r] = __float2bfloat16(v.z * rn);
        smT[c4 + 3][r] = __float2bfloat16(v.w * rn);
    }
    __syncthreads();
    #pragma unroll
    for (int s = tid; s < 512; s += 256) {
        int pl = s >> 3, i8 = (s & 7) * 8;
        *(uint4*)(dst + (size_t)(p0 + pl) * BN + i0 + i8) = *(uint4*)&smT[pl][i8];
    }
}

// ---------------- bf16 tensor-core Gram + multi-gamma RBF + 16x16 histogram ----------------
#define PITCH 72
#define KC 64

__global__ __launch_bounds__(256) void gram_mma_kernel() {
    const int T = BN / 128;                 // 32
    int set = blockIdx.y;
    const __nv_bfloat16* X = g_bf[set];

    int idx = blockIdx.x;                   // upper-triangle decode
    int ti = 0;
    while (idx >= T - ti) { idx -= T - ti; ti++; }
    int tj = ti + idx;
    int i0 = ti * 128, j0 = tj * 128;
    bool diag = (ti == tj);

    __shared__ __nv_bfloat16 As[128 * PITCH];
    __shared__ __nv_bfloat16 Bs[128 * PITCH];
    __shared__ float bins[8][256];
    __shared__ float sqi[128], sqj[128];
    __shared__ int   ci_s[128], cj_s[128];

    int tid = threadIdx.x;
    int wid = tid >> 5, lane = tid & 31;
    for (int b = tid; b < 2048; b += 256) ((float*)bins)[b] = 0.f;
    if (tid < 128) { sqi[tid] = g_sq[set][i0 + tid]; ci_s[tid] = g_cls[i0 + tid]; }
    else { int t = tid - 128; sqj[t] = g_sq[set][j0 + t]; cj_s[t] = g_cls[j0 + t]; }

    int wm = wid >> 2, wn = wid & 3;

    float acc[4][4][4];
    #pragma unroll
    for (int mi = 0; mi < 4; mi++)
        #pragma unroll
        for (int ni = 0; ni < 4; ni++)
            #pragma unroll
            for (int r = 0; r < 4; r++) acc[mi][ni][r] = 0.f;

    unsigned as_base = smem_u32(As);
    unsigned bs_base = smem_u32(Bs);

    for (int kc = 0; kc < DN; kc += KC) {
        __syncthreads();
        #pragma unroll
        for (int p = 0; p < 4; p++) {
            int v = tid + p * 256;
            int row = v >> 3, c8 = v & 7;
            uint4 da = *(const uint4*)(X + (size_t)(i0 + row) * DN + kc + c8 * 8);
            *(uint4*)(As + row * PITCH + c8 * 8) = da;
            uint4 db = *(const uint4*)(X + (size_t)(j0 + row) * DN + kc + c8 * 8);
            *(uint4*)(Bs + row * PITCH + c8 * 8) = db;
        }
        __syncthreads();
        #pragma unroll
        for (int ks = 0; ks < KC; ks += 16) {
            unsigned a[4][4], b[4][2];
            #pragma unroll
            for (int mi = 0; mi < 4; mi++) {
                int row = wm * 64 + mi * 16 + (lane & 15);
                unsigned addr = as_base + (row * PITCH + ks + (lane >> 4) * 8) * 2;
                asm volatile("ldmatrix.sync.aligned.m8n8.x4.shared.b16 {%0,%1,%2,%3}, [%4];"
                             : "=r"(a[mi][0]), "=r"(a[mi][1]), "=r"(a[mi][2]), "=r"(a[mi][3])
                             : "r"(addr));
            }
            #pragma unroll
            for (int p = 0; p < 2; p++) {
                int g = lane >> 3, r = lane & 7;
                int row = wn * 32 + p * 16 + (g >> 1) * 8 + r;
                unsigned addr = bs_base + (row * PITCH + ks + (g & 1) * 8) * 2;
                unsigned r0, r1, r2, r3;
                asm volatile("ldmatrix.sync.aligned.m8n8.x4.shared.b16 {%0,%1,%2,%3}, [%4];"
                             : "=r"(r0), "=r"(r1), "=r"(r2), "=r"(r3) : "r"(addr));
                b[p * 2][0] = r0;  b[p * 2][1] = r1;
                b[p * 2 + 1][0] = r2;  b[p * 2 + 1][1] = r3;
            }
            #pragma unroll
            for (int mi = 0; mi < 4; mi++)
                #pragma unroll
                for (int ni = 0; ni < 4; ni++) {
                    asm volatile(
                        "mma.sync.aligned.m16n8k16.row.col.f32.bf16.bf16.f32 "
                        "{%0,%1,%2,%3}, {%4,%5,%6,%7}, {%8,%9}, {%0,%1,%2,%3};"
                        : "+f"(acc[mi][ni][0]), "+f"(acc[mi][ni][1]),
                          "+f"(acc[mi][ni][2]), "+f"(acc[mi][ni][3])
                        : "r"(a[mi][0]), "r"(a[mi][1]), "r"(a[mi][2]), "r"(a[mi][3]),
                          "r"(b[ni][0]), "r"(b[ni][1]));
                }
        }
    }

    #pragma unroll
    for (int mi = 0; mi < 4; mi++) {
        int rbase = wm * 64 + mi * 16 + (lane >> 2);
        #pragma unroll
        for (int ni = 0; ni < 4; ni++) {
            int cbase = wn * 32 + ni * 8 + (lane & 3) * 2;
            #pragma unroll
            for (int rr = 0; rr < 2; rr++) {
                int il = rbase + rr * 8;
                int aCls = ci_s[il];
                if (aCls < 0) continue;
                float si = sqi[il];
                #pragma unroll
                for (int cc = 0; cc < 2; cc++) {
                    int jl = cbase + cc;
                    int bCls = cj_s[jl];
                    if (bCls < 0) continue;
                    if (diag) {
                        if (jl < il) continue;
                        if (jl == il) { atomicAdd(&bins[wid][aCls * 17], 2.5f); continue; }
                    }
                    float dot = acc[mi][ni][rr * 2 + cc];
                    float D = si + sqj[jl] - 2.f * dot;
                    float Kv = __expf(-0.01f * D);
                    if (D < 340.f) {
                        Kv += __expf(-0.1f * D) + __expf(-D)
                            + __expf(-10.f * D) + __expf(-100.f * D);
                    }
                    atomicAdd(&bins[wid][aCls * 16 + bCls], Kv);
                }
            }
        }
    }
    __syncthreads();
    {
        float s = 0.f;
        #pragma unroll
        for (int w = 0; w < 8; w++) s += bins[w][tid];
        atomicAdd(&g_G[set][tid], s);
    }
}

// ---------------- column sums of normalized bf16 feats (contiguous) ----------------
__global__ void colsumT_kernel() {
    int m = blockIdx.y;
    int p = blockIdx.x * 8 + (threadIdx.x >> 5);
    int lane = threadIdx.x & 31;
    const __nv_bfloat16* src = g_nfT[m] + (size_t)p * BN;
    float s = 0.f;
    #pragma unroll
    for (int it = 0; it < 16; it++) {
        uint4 v = *(const uint4*)(src + lane * 8 + it * 256);
        const __nv_bfloat16* t = (const __nv_bfloat16*)&v;
        #pragma unroll
        for (int j = 0; j < 8; j++) s += __bfloat162float(t[j]);
    }
    #pragma unroll
    for (int o = 16; o; o >>= 1) s += __shfl_xor_sync(0xffffffffu, s, o);
    if (lane == 0) g_colsum[m][p] = s;
}

// ---------------- HSIC bf16 MMA: g_Ms[pair][split] = Cn^T * Sn (k-chunk) ----------------
__global__ __launch_bounds__(256) void hsic_mma_kernel() {
    int tile = blockIdx.x;                 // 0..3
    int split = blockIdx.y;                // 0..15
    int pair = blockIdx.z;
    int tp = (tile >> 1) * 128, tq = (tile & 1) * 128;
    int k0 = split * 256;
    const __nv_bfloat16* A = g_nfT[2 * pair];
    const __nv_bfloat16* Bm = g_nfT[2 * pair + 1];
    float* out = g_Ms[pair][split];

    __shared__ __nv_bfloat16 As[128 * PITCH];
    __shared__ __nv_bfloat16 Bs[128 * PITCH];

    int tid = threadIdx.x;
    int wid = tid >> 5, lane = tid & 31;
    int wm = wid >> 2, wn = wid & 3;

    float acc[4][4][4];
    #pragma unroll
    for (int mi = 0; mi < 4; mi++)
        #pragma unroll
        for (int ni = 0; ni < 4; ni++)
            #pragma unroll
            for (int r = 0; r < 4; r++) acc[mi][ni][r] = 0.f;

    unsigned as_base = smem_u32(As);
    unsigned bs_base = smem_u32(Bs);

    for (int kc = 0; kc < 256; kc += KC) {
        __syncthreads();
        #pragma unroll
        for (int p = 0; p < 4; p++) {
            int v = tid + p * 256;
            int row = v >> 3, c8 = v & 7;
            uint4 da = *(const uint4*)(A + (size_t)(tp + row) * BN + k0 + kc + c8 * 8);
            *(uint4*)(As + row * PITCH + c8 * 8) = da;
            uint4 db = *(const uint4*)(Bm + (size_t)(tq + row) * BN + k0 + kc + c8 * 8);
            *(uint4*)(Bs + row * PITCH + c8 * 8) = db;
        }
        __syncthreads();
        #pragma unroll
        for (int ks = 0; ks < KC; ks += 16) {
            unsigned a[4][4], b[4][2];
            #pragma unroll
            for (int mi = 0; mi < 4; mi++) {
                int row = wm * 64 + mi * 16 + (lane & 15);
                unsigned addr = as_base + (row * PITCH + ks + (lane >> 4) * 8) * 2;
                asm volatile("ldmatrix.sync.aligned.m8n8.x4.shared.b16 {%0,%1,%2,%3}, [%4];"
                             : "=r"(a[mi][0]), "=r"(a[mi][1]), "=r"(a[mi][2]), "=r"(a[mi][3])
                             : "r"(addr));
            }
            #pragma unroll
            for (int p = 0; p < 2; p++) {
                int g = lane >> 3, r = lane & 7;
                int row = wn * 32 + p * 16 + (g >> 1) * 8 + r;
                unsigned addr = bs_base + (row * PITCH + ks + (g & 1) * 8) * 2;
                unsigned r0, r1, r2, r3;
                asm volatile("ldmatrix.sync.aligned.m8n8.x4.shared.b16 {%0,%1,%2,%3}, [%4];"
                             : "=r"(r0), "=r"(r1), "=r"(r2), "=r"(r3) : "r"(addr));
                b[p * 2][0] = r0;  b[p * 2][1] = r1;
                b[p * 2 + 1][0] = r2;  b[p * 2 + 1][1] = r3;
            }
            #pragma unroll
            for (int mi = 0; mi < 4; mi++)
                #pragma unroll
                for (int ni = 0; ni < 4; ni++) {
                    asm volatile(
                        "mma.sync.aligned.m16n8k16.row.col.f32.bf16.bf16.f32 "
                        "{%0,%1,%2,%3}, {%4,%5,%6,%7}, {%8,%9}, {%0,%1,%2,%3};"
                        : "+f"(acc[mi][ni][0]), "+f"(acc[mi][ni][1]),
                          "+f"(acc[mi][ni][2]), "+f"(acc[mi][ni][3])
                        : "r"(a[mi][0]), "r"(a[mi][1]), "r"(a[mi][2]), "r"(a[mi][3]),
                          "r"(b[ni][0]), "r"(b[ni][1]));
                }
        }
    }

    #pragma unroll
    for (int mi = 0; mi < 4; mi++) {
        #pragma unroll
        for (int ni = 0; ni < 4; ni++) {
            #pragma unroll
            for (int rr = 0; rr < 2; rr++) {
                int row = tp + wm * 64 + mi * 16 + (lane >> 2) + rr * 8;
                int col = tq + wn * 32 + ni * 8 + (lane & 3) * 2;
                float2 v = make_float2(acc[mi][ni][rr * 2], acc[mi][ni][rr * 2 + 1]);
                *(float2*)(out + row * 256 + col) = v;
            }
        }
    }
}

// ---------------- fused focal + CE losses ----------------
__global__ void smalloss_kernel(const float* __restrict__ l1, const int* __restrict__ b1,
                                const float* __restrict__ l2, const int* __restrict__ b2,
                                const float* __restrict__ l3, const int* __restrict__ b3,
                                const float* __restrict__ vsv, const float* __restrict__ vst,
                                const int* __restrict__ dom,
                                const unsigned char* __restrict__ mask) {
    int task = blockIdx.y;
    int r = blockIdx.x * blockDim.x + threadIdx.x;
    float loss = 0.f;
    if (r < BN && mask[r]) {
        if (task < 3) {
            const float* lg = (task == 0) ? l1 : (task == 1) ? l2 : l3;
            const int* lb = (task == 0) ? b1 : (task == 1) ? b2 : b3;
            int nc = (task == 0) ? 4 : (task == 1) ? 6 : 3;
            float x[6];
            float mx = -1e30f;
            for (int c = 0; c < nc; c++) { x[c] = lg[r * nc + c]; mx = fmaxf(mx, x[c]); }
            float se = 0.f, sx = 0.f;
            for (int c = 0; c < nc; c++) { se += expf(x[c] - mx); sx += x[c]; }
            float logZ = mx + logf(se);
            int t = lb[r];
            float ce = logZ - (0.9f * x[t] + (0.1f / (float)nc) * sx);
            float pt = expf(x[t] - logZ);
            float om = 1.f - pt;
            loss = ce * om * om;
        } else {
            const float* lg = (task == 3) ? vsv : vst;
            float x0 = lg[r * 4 + 0], x1 = lg[r * 4 + 1], x2 = lg[r * 4 + 2], x3 = lg[r * 4 + 3];
            float mx = fmaxf(fmaxf(x0, x1), fmaxf(x2, x3));
            float se = expf(x0 - mx) + expf(x1 - mx) + expf(x2 - mx) + expf(x3 - mx);
            float logZ = mx + logf(se);
            int t = dom[r];
            float xt = (t == 0) ? x0 : (t == 1) ? x1 : (t == 2) ? x2 : x3;
            loss = logZ - xt;
        }
    }
    __shared__ float red[256];
    red[threadIdx.x] = loss;
    __syncthreads();
    for (int s = 128; s; s >>= 1) { if (threadIdx.x < s) red[threadIdx.x] += red[threadIdx.x + s]; __syncthreads(); }
    if (threadIdx.x == 0) {
        int slot = (task < 3) ? task : (task + 1);   // 0,1,2,4,5
        atomicAdd(&g_scal[slot], red[0]);
    }
}

// ---------------- reconstruction MSE (summed) ----------------
__global__ void recon_kernel(const float* __restrict__ a, const float* __restrict__ b,
                             const float* __restrict__ c, const float* __restrict__ d) {
    const int n4 = BN * HN / 4;
    float s = 0.f;
    for (int i = blockIdx.x * blockDim.x + threadIdx.x; i < n4; i += gridDim.x * blockDim.x) {
        float4 va = ((const float4*)a)[i], vb = ((const float4*)b)[i];
        float dx = va.x - vb.x, dy = va.y - vb.y, dz = va.z - vb.z, dw = va.w - vb.w;
        s += dx * dx + dy * dy + dz * dz + dw * dw;
        float4 vc = ((const float4*)c)[i], vd = ((const float4*)d)[i];
        dx = vc.x - vd.x; dy = vc.y - vd.y; dz = vc.z - vd.z; dw = vc.w - vd.w;
        s += dx * dx + dy * dy + dz * dz + dw * dw;
    }
    __shared__ float red[256];
    red[threadIdx.x] = s;
    __syncthreads();
    for (int st = 128; st; st >>= 1) { if (threadIdx.x < st) red[threadIdx.x] += red[threadIdx.x + st]; __syncthreads(); }
    if (threadIdx.x == 0) atomicAdd(&g_scal[6], red[0]);
}

// ---------------- HSIC reduction: sum splits, center, square, accumulate ----------------
__global__ void hsic_reduce_kernel() {
    int tid = threadIdx.x;
    const float invB = 1.f / (float)BN;
    float local = 0.f;
    #pragma unroll
    for (int rep = 0; rep < 2; rep++) {
        int e = blockIdx.x * 512 + rep * 256 + tid;
        int p = e >> 8, q = e & 255;
        float s0 = 0.f, s1 = 0.f;
        #pragma unroll
        for (int s = 0; s < 16; s++) {
            s0 += g_Ms[0][s][e];
            s1 += g_Ms[1][s][e];
        }
        float m0 = s0 - g_colsum[0][p] * g_colsum[1][q] * invB;
        float m1 = s1 - g_colsum[2][p] * g_colsum[3][q] * invB;
        local += m0 * m0 + m1 * m1;
    }
    __shared__ float red[256];
    red[tid] = local;
    __syncthreads();
    for (int s = 128; s; s >>= 1) { if (tid < s) red[tid] += red[tid + s]; __syncthreads(); }
    if (tid == 0) atomicAdd(&g_scal[7], red[0]);
}

// ---------------- combine everything into the scalar ----------------
__global__ void combine_kernel(float* __restrict__ out) {
    if (threadIdx.x != 0) return;
    float hsic_sum = g_scal[7] / (4095.f * 4095.f);

    float mmd[2];
    for (int s = 0; s < 2; s++) {
        float loss = 0.f, count = 0.f;
        for (int lab = 0; lab < 4; lab++)
            for (int d1 = 0; d1 < 4; d1++) {
                int a = lab * 4 + d1;
                float n1 = g_cnt[a];
                for (int d2 = d1 + 1; d2 < 4; d2++) {
                    int b = lab * 4 + d2;
                    float n2 = g_cnt[b];
                    if (n1 > 1.f && n2 > 1.f) {
                        float ga = 2.f * g_G[s][a * 16 + a];
                        float gb = 2.f * g_G[s][b * 16 + b];
                        float gab = g_G[s][a * 16 + b] + g_G[s][b * 16 + a];
                        float m1m = fmaxf(n1, 1.f), m2m = fmaxf(n2, 1.f);
                        float term = ga / (m1m * m1m) + gb / (m2m * m2m)
                                   - 2.f * gab / fmaxf(n1 * n2, 1.f);
                        loss += term;
                        count += 1.f;
                    }
                }
            }
        mmd[s] = loss / fmaxf(count, 1.f);
    }

    float msum = fmaxf(g_scal[3], 1.f);
    float total = 0.4f * g_scal[0] / msum + 0.3f * g_scal[1] / msum + 0.3f * g_scal[2] / msum;
    total += 0.1f * (g_scal[4] / msum + g_scal[5] / msum + mmd[0] + mmd[1]);
    total += 0.1f * hsic_sum;
    total += g_scal[6] / (float)(BN * HN);
    out[0] = total;
}

// ---------------- launch ----------------
extern "C" void kernel_launch(void* const* d_in, const int* in_sizes, int n_in,
                              void* d_out, int out_size) {
    (void)in_sizes; (void)n_in; (void)out_size;
    const float* logits1 = (const float*)d_in[0];
    const int*   labels1 = (const int*)d_in[1];
    const float* logits2 = (const float*)d_in[2];
    const int*   labels2 = (const int*)d_in[3];
    const float* logits3 = (const float*)d_in[4];
    const int*   labels3 = (const int*)d_in[5];
    const float* c_v  = (const float*)d_in[6];
    const float* s_v  = (const float*)d_in[7];
    const float* c_t  = (const float*)d_in[8];
    const float* s_t  = (const float*)d_in[9];
    const float* v_sv = (const float*)d_in[10];
    const float* v_st = (const float*)d_in[11];
    const int*   dom  = (const int*)d_in[12];
    const unsigned char* mask = (const unsigned char*)d_in[13];
    const float* hir = (const float*)d_in[14];
    const float* hio = (const float*)d_in[15];
    const float* htr = (const float*)d_in[16];
    const float* hto = (const float*)d_in[17];

    zero_kernel<<<1, 256>>>();
    precompute_kernel<<<512, 256>>>(c_v, c_t, labels1, dom, mask);
    norms_kernel<<<dim3(512, 4), 256>>>(c_v, s_v, c_t, s_t);
    transposeN_kernel<<<dim3(64, 4, 4), 256>>>(c_v, s_v, c_t, s_t);
    gram_mma_kernel<<<dim3(528, 2), 256>>>();          // position 5 for ncu -s 5 -c 1
    colsumT_kernel<<<dim3(32, 4), 256>>>();
    hsic_mma_kernel<<<dim3(4, 16, 2), 256>>>();
    smalloss_kernel<<<dim3(16, 5), 256>>>(logits1, labels1, logits2, labels2,
                                          logits3, labels3, v_sv, v_st, dom, mask);
    recon_kernel<<<256, 256>>>(hir, hio, htr, hto);
    hsic_reduce_kernel<<<128, 256>>>();
    combine_kernel<<<1, 32>>>((float*)d_out);
}

// round 6
// speedup vs baseline: 3.4064x; 1.1889x over previous
#include <cuda_runtime.h>
#include <cuda_bf16.h>
#include <math.h>

#define BN 4096
#define DN 256
#define HN 768

// ---------------- device scratch (static, allocation-free) ----------------
__device__ float g_G[2][256];      // single-counted 16x16 Ksum histograms (atomic, zeroed in A)
__device__ float g_Ms[2][16][65536]; // per-k-split HSIC cross products (fully written)
__device__ float g_colsum[4][256]; // column sums of normalized bf16 feats (atomic, zeroed in A)
__device__ float g_rn[4][BN];      // 1/row-norm of c_v, s_v, c_t, s_t
__device__ __nv_bfloat16 g_nfT[4][DN * BN]; // normalized, transposed (p-major, i contig)
__device__ float g_sq[2][BN];      // row squared norms of bf16(c_v), bf16(c_t)
__device__ int   g_cls[BN];        // label*4+domain, or -1 if masked out
__device__ __nv_bfloat16 g_bf[2][BN * DN];  // bf16 copies of c_v, c_t
__device__ float g_lpart[5][16];   // small-loss block partials (written)
__device__ float g_rpart[512];     // recon block partials (written)
__device__ float g_hpart[128];     // hsic frob block partials (written)
__device__ int   g_ticket;         // = 0 statically; self-resetting

__device__ __forceinline__ unsigned smem_u32(const void* p) {
    return (unsigned)__cvta_generic_to_shared(p);
}

// =======================================================================
// Kernel A: prep — grid (512, 6), 256 threads
//  role 0: bf16 convert + bf16 sq norms + fp32 norms (c_v, c_t) + cls
//  role 1: fp32 norms s_v;  role 2: fp32 norms s_t
//  role 3: recon MSE partials;  role 4: focal/CE partials
//  role 5: zero g_G / g_colsum
// =======================================================================
__global__ void prep_kernel(const float* __restrict__ cv, const float* __restrict__ ct,
                            const float* __restrict__ sv, const float* __restrict__ st,
                            const int* __restrict__ lab, const int* __restrict__ dom,
                            const unsigned char* __restrict__ mask,
                            const float* __restrict__ l1, const int* __restrict__ b1,
                            const float* __restrict__ l2, const int* __restrict__ b2,
                            const float* __restrict__ l3, const int* __restrict__ b3,
                            const float* __restrict__ vsv, const float* __restrict__ vst,
                            const float* __restrict__ hir, const float* __restrict__ hio,
                            const float* __restrict__ htr, const float* __restrict__ hto) {
    int role = blockIdx.y;
    int bx = blockIdx.x;
    int tid = threadIdx.x;

    if (role == 0) {
        int r = (bx * 256 + tid) >> 5;
        int lane = tid & 31;
        #pragma unroll
        for (int set = 0; set < 2; set++) {
            const float* src = set ? ct : cv;
            const float4* p = (const float4*)(src + (size_t)r * DN);
            float4 v0 = p[lane * 2], v1 = p[lane * 2 + 1];
            float s32 = v0.x * v0.x + v0.y * v0.y + v0.z * v0.z + v0.w * v0.w
                      + v1.x * v1.x + v1.y * v1.y + v1.z * v1.z + v1.w * v1.w;
            __nv_bfloat16 t[8];
            t[0] = __float2bfloat16(v0.x); t[1] = __float2bfloat16(v0.y);
            t[2] = __float2bfloat16(v0.z); t[3] = __float2bfloat16(v0.w);
            t[4] = __float2bfloat16(v1.x); t[5] = __float2bfloat16(v1.y);
            t[6] = __float2bfloat16(v1.z); t[7] = __float2bfloat16(v1.w);
            float sbf = 0.f;
            #pragma unroll
            for (int i = 0; i < 8; i++) { float f = __bfloat162float(t[i]); sbf += f * f; }
            #pragma unroll
            for (int o = 16; o; o >>= 1) {
                s32 += __shfl_xor_sync(0xffffffffu, s32, o);
                sbf += __shfl_xor_sync(0xffffffffu, sbf, o);
            }
            if (lane == 0) {
                g_sq[set][r] = sbf;
                g_rn[set * 2][r] = 1.f / fmaxf(sqrtf(s32), 1e-12f);
            }
            *(uint4*)(g_bf[set] + (size_t)r * DN + lane * 8) = *(uint4*)t;
        }
        if (lane == 0) {
            int c = lab[r] * 4 + dom[r];
            g_cls[r] = mask[r] ? c : -1;
        }
    } else if (role <= 2) {
        const float* src = (role == 1) ? sv : st;
        int m = (role == 1) ? 1 : 3;
        int r = (bx * 256 + tid) >> 5;
        int lane = tid & 31;
        const float4* p = (const float4*)(src + (size_t)r * DN);
        float4 v0 = p[lane], v1 = p[lane + 32];
        float s = v0.x * v0.x + v0.y * v0.y + v0.z * v0.z + v0.w * v0.w
                + v1.x * v1.x + v1.y * v1.y + v1.z * v1.z + v1.w * v1.w;
        #pragma unroll
        for (int o = 16; o; o >>= 1) s += __shfl_xor_sync(0xffffffffu, s, o);
        if (lane == 0) g_rn[m][r] = 1.f / fmaxf(sqrtf(s), 1e-12f);
    } else if (role == 3) {
        const int n4 = BN * HN / 4;
        const int stride = 512 * 256;
        float s = 0.f;
        for (int i = bx * 256 + tid; i < n4; i += stride) {
            float4 va = ((const float4*)hir)[i], vb = ((const float4*)hio)[i];
            float dx = va.x - vb.x, dy = va.y - vb.y, dz = va.z - vb.z, dw = va.w - vb.w;
            s += dx * dx + dy * dy + dz * dz + dw * dw;
            float4 vc = ((const float4*)htr)[i], vd = ((const float4*)hto)[i];
            dx = vc.x - vd.x; dy = vc.y - vd.y; dz = vc.z - vd.z; dw = vc.w - vd.w;
            s += dx * dx + dy * dy + dz * dz + dw * dw;
        }
        __shared__ float red[256];
        red[tid] = s;
        __syncthreads();
        for (int st_ = 128; st_; st_ >>= 1) { if (tid < st_) red[tid] += red[tid + st_]; __syncthreads(); }
        if (tid == 0) g_rpart[bx] = red[0];
    } else if (role == 4) {
        if (bx >= 80) return;
        int task = bx >> 4, sub = bx & 15;
        int r = sub * 256 + tid;
        float loss = 0.f;
        if (mask[r]) {
            if (task < 3) {
                const float* lg = (task == 0) ? l1 : (task == 1) ? l2 : l3;
                const int* lb = (task == 0) ? b1 : (task == 1) ? b2 : b3;
                int nc = (task == 0) ? 4 : (task == 1) ? 6 : 3;
                float x[6];
                float mx = -1e30f;
                for (int c = 0; c < nc; c++) { x[c] = lg[r * nc + c]; mx = fmaxf(mx, x[c]); }
                float se = 0.f, sx = 0.f;
                for (int c = 0; c < nc; c++) { se += expf(x[c] - mx); sx += x[c]; }
                float logZ = mx + logf(se);
                int t = lb[r];
                float ce = logZ - (0.9f * x[t] + (0.1f / (float)nc) * sx);
                float pt = expf(x[t] - logZ);
                float om = 1.f - pt;
                loss = ce * om * om;
            } else {
                const float* lg = (task == 3) ? vsv : vst;
                float x0 = lg[r * 4 + 0], x1 = lg[r * 4 + 1], x2 = lg[r * 4 + 2], x3 = lg[r * 4 + 3];
                float mx = fmaxf(fmaxf(x0, x1), fmaxf(x2, x3));
                float se = expf(x0 - mx) + expf(x1 - mx) + expf(x2 - mx) + expf(x3 - mx);
                float logZ = mx + logf(se);
                int t = dom[r];
                float xt = (t == 0) ? x0 : (t == 1) ? x1 : (t == 2) ? x2 : x3;
                loss = logZ - xt;
            }
        }
        __shared__ float red[256];
        red[tid] = loss;
        __syncthreads();
        for (int st_ = 128; st_; st_ >>= 1) { if (tid < st_) red[tid] += red[tid + st_]; __syncthreads(); }
        if (tid == 0) g_lpart[task][sub] = red[0];
    } else {
        if (bx == 0) { for (int e = tid; e < 512; e += 256) ((float*)g_G)[e] = 0.f; }
        else if (bx == 1) { for (int e = tid; e < 1024; e += 256) ((float*)g_colsum)[e] = 0.f; }
    }
}

// =======================================================================
// Kernel B: normalize + transpose to bf16 (p-major) + fused column sums
// =======================================================================
__global__ void transposeN_kernel(const float* __restrict__ in0, const float* __restrict__ in1,
                                  const float* __restrict__ in2, const float* __restrict__ in3) {
    int m = blockIdx.z;
    const float* src = (m == 0) ? in0 : (m == 1) ? in1 : (m == 2) ? in2 : in3;
    __nv_bfloat16* dst = g_nfT[m];
    int i0 = blockIdx.x * 64, p0 = blockIdx.y * 64;

    __shared__ __nv_bfloat16 smT[64][88];
    __shared__ float rns[64];
    int tid = threadIdx.x;
    if (tid < 64) rns[tid] = g_rn[m][i0 + tid];
    __syncthreads();

    #pragma unroll
    for (int s = tid; s < 1024; s += 256) {
        int r = s >> 4, c4 = (s & 15) * 4;
        float4 v = *(const float4*)(src + (size_t)(i0 + r) * DN + p0 + c4);
        float rn = rns[r];
        smT[c4 + 0][r] = __float2bfloat16(v.x * rn);
        smT[c4 + 1][r] = __float2bfloat16(v.y * rn);
        smT[c4 + 2][r] = __float2bfloat16(v.z * rn);
        smT[c4 + 3][r] = __float2bfloat16(v.w * rn);
    }
    __syncthreads();
    #pragma unroll
    for (int s = tid; s < 512; s += 256) {
        int pl = s >> 3, i8 = (s & 7) * 8;
        *(uint4*)(dst + (size_t)(p0 + pl) * BN + i0 + i8) = *(uint4*)&smT[pl][i8];
    }
    if (tid < 64) {
        float s = 0.f;
        #pragma unroll
        for (int i = 0; i < 64; i++) s += __bfloat162float(smT[tid][i]);
        atomicAdd(&g_colsum[m][p0 + tid], s);
    }
}

// =======================================================================
// Kernel CD: gram (blocks 0..1055) + hsic_mma (blocks 1056..1183)
// =======================================================================
#define PITCH 72
#define KC 64

__global__ __launch_bounds__(256) void gram_hsic_kernel() {
    __shared__ __nv_bfloat16 As[128 * PITCH];
    __shared__ __nv_bfloat16 Bs[128 * PITCH];
    __shared__ float bins[8][256];
    __shared__ float sqi[128], sqj[128];
    __shared__ int   ci_s[128], cj_s[128];

    int tid = threadIdx.x;
    int wid = tid >> 5, lane = tid & 31;
    int wm = wid >> 2, wn = wid & 3;
    unsigned as_base = smem_u32(As);
    unsigned bs_base = smem_u32(Bs);

    float acc[4][4][4];
    #pragma unroll
    for (int mi = 0; mi < 4; mi++)
        #pragma unroll
        for (int ni = 0; ni < 4; ni++)
            #pragma unroll
            for (int r = 0; r < 4; r++) acc[mi][ni][r] = 0.f;

    if (blockIdx.x < 1056) {
        // ---------------- GRAM path ----------------
        const int T = BN / 128;
        int set = (blockIdx.x >= 528) ? 1 : 0;
        int idx = blockIdx.x - set * 528;
        const __nv_bfloat16* X = g_bf[set];
        int ti = 0;
        while (idx >= T - ti) { idx -= T - ti; ti++; }
        int tj = ti + idx;
        int i0 = ti * 128, j0 = tj * 128;
        bool diag = (ti == tj);

        for (int b = tid; b < 2048; b += 256) ((float*)bins)[b] = 0.f;
        if (tid < 128) { sqi[tid] = g_sq[set][i0 + tid]; ci_s[tid] = g_cls[i0 + tid]; }
        else { int t = tid - 128; sqj[t] = g_sq[set][j0 + t]; cj_s[t] = g_cls[j0 + t]; }

        for (int kc = 0; kc < DN; kc += KC) {
            __syncthreads();
            #pragma unroll
            for (int p = 0; p < 4; p++) {
                int v = tid + p * 256;
                int row = v >> 3, c8 = v & 7;
                uint4 da = *(const uint4*)(X + (size_t)(i0 + row) * DN + kc + c8 * 8);
                *(uint4*)(As + row * PITCH + c8 * 8) = da;
                uint4 db = *(const uint4*)(X + (size_t)(j0 + row) * DN + kc + c8 * 8);
                *(uint4*)(Bs + row * PITCH + c8 * 8) = db;
            }
            __syncthreads();
            #pragma unroll
            for (int ks = 0; ks < KC; ks += 16) {
                unsigned a[4][4], b[4][2];
                #pragma unroll
                for (int mi = 0; mi < 4; mi++) {
                    int row = wm * 64 + mi * 16 + (lane & 15);
                    unsigned addr = as_base + (row * PITCH + ks + (lane >> 4) * 8) * 2;
                    asm volatile("ldmatrix.sync.aligned.m8n8.x4.shared.b16 {%0,%1,%2,%3}, [%4];"
                                 : "=r"(a[mi][0]), "=r"(a[mi][1]), "=r"(a[mi][2]), "=r"(a[mi][3])
                                 : "r"(addr));
                }
                #pragma unroll
                for (int p = 0; p < 2; p++) {
                    int g = lane >> 3, r = lane & 7;
                    int row = wn * 32 + p * 16 + (g >> 1) * 8 + r;
                    unsigned addr = bs_base + (row * PITCH + ks + (g & 1) * 8) * 2;
                    unsigned r0, r1, r2, r3;
                    asm volatile("ldmatrix.sync.aligned.m8n8.x4.shared.b16 {%0,%1,%2,%3}, [%4];"
                                 : "=r"(r0), "=r"(r1), "=r"(r2), "=r"(r3) : "r"(addr));
                    b[p * 2][0] = r0;  b[p * 2][1] = r1;
                    b[p * 2 + 1][0] = r2;  b[p * 2 + 1][1] = r3;
                }
                #pragma unroll
                for (int mi = 0; mi < 4; mi++)
                    #pragma unroll
                    for (int ni = 0; ni < 4; ni++) {
                        asm volatile(
                            "mma.sync.aligned.m16n8k16.row.col.f32.bf16.bf16.f32 "
                            "{%0,%1,%2,%3}, {%4,%5,%6,%7}, {%8,%9}, {%0,%1,%2,%3};"
                            : "+f"(acc[mi][ni][0]), "+f"(acc[mi][ni][1]),
                              "+f"(acc[mi][ni][2]), "+f"(acc[mi][ni][3])
                            : "r"(a[mi][0]), "r"(a[mi][1]), "r"(a[mi][2]), "r"(a[mi][3]),
                              "r"(b[ni][0]), "r"(b[ni][1]));
                    }
            }
        }

        #pragma unroll
        for (int mi = 0; mi < 4; mi++) {
            int rbase = wm * 64 + mi * 16 + (lane >> 2);
            #pragma unroll
            for (int ni = 0; ni < 4; ni++) {
                int cbase = wn * 32 + ni * 8 + (lane & 3) * 2;
                #pragma unroll
                for (int rr = 0; rr < 2; rr++) {
                    int il = rbase + rr * 8;
                    int aCls = ci_s[il];
                    if (aCls < 0) continue;
                    float si = sqi[il];
                    #pragma unroll
                    for (int cc = 0; cc < 2; cc++) {
                        int jl = cbase + cc;
                        int bCls = cj_s[jl];
                        if (bCls < 0) continue;
                        if (diag) {
                            if (jl < il) continue;
                            if (jl == il) { atomicAdd(&bins[wid][aCls * 17], 2.5f); continue; }
                        }
                        float dot = acc[mi][ni][rr * 2 + cc];
                        float D = si + sqj[jl] - 2.f * dot;
                        float Kv = __expf(-0.01f * D);
                        if (D < 340.f) {
                            Kv += __expf(-0.1f * D) + __expf(-D)
                                + __expf(-10.f * D) + __expf(-100.f * D);
                        }
                        atomicAdd(&bins[wid][aCls * 16 + bCls], Kv);
                    }
                }
            }
        }
        __syncthreads();
        {
            float s = 0.f;
            #pragma unroll
            for (int w = 0; w < 8; w++) s += bins[w][tid];
            atomicAdd(&g_G[set][tid], s);
        }
    } else {
        // ---------------- HSIC MMA path ----------------
        int b2 = blockIdx.x - 1056;
        int tile = b2 & 3, split = (b2 >> 2) & 15, pair = b2 >> 6;
        int tp = (tile >> 1) * 128, tq = (tile & 1) * 128;
        int k0 = split * 256;
        const __nv_bfloat16* A = g_nfT[2 * pair];
        const __nv_bfloat16* Bm = g_nfT[2 * pair + 1];
        float* out = g_Ms[pair][split];

        for (int kc = 0; kc < 256; kc += KC) {
            __syncthreads();
            #pragma unroll
            for (int p = 0; p < 4; p++) {
                int v = tid + p * 256;
                int row = v >> 3, c8 = v & 7;
                uint4 da = *(const uint4*)(A + (size_t)(tp + row) * BN + k0 + kc + c8 * 8);
                *(uint4*)(As + row * PITCH + c8 * 8) = da;
                uint4 db = *(const uint4*)(Bm + (size_t)(tq + row) * BN + k0 + kc + c8 * 8);
                *(uint4*)(Bs + row * PITCH + c8 * 8) = db;
            }
            __syncthreads();
            #pragma unroll
            for (int ks = 0; ks < KC; ks += 16) {
                unsigned a[4][4], b[4][2];
                #pragma unroll
                for (int mi = 0; mi < 4; mi++) {
                    int row = wm * 64 + mi * 16 + (lane & 15);
                    unsigned addr = as_base + (row * PITCH + ks + (lane >> 4) * 8) * 2;
                    asm volatile("ldmatrix.sync.aligned.m8n8.x4.shared.b16 {%0,%1,%2,%3}, [%4];"
                                 : "=r"(a[mi][0]), "=r"(a[mi][1]), "=r"(a[mi][2]), "=r"(a[mi][3])
                                 : "r"(addr));
                }
                #pragma unroll
                for (int p = 0; p < 2; p++) {
                    int g = lane >> 3, r = lane & 7;
                    int row = wn * 32 + p * 16 + (g >> 1) * 8 + r;
                    unsigned addr = bs_base + (row * PITCH + ks + (g & 1) * 8) * 2;
                    unsigned r0, r1, r2, r3;
                    asm volatile("ldmatrix.sync.aligned.m8n8.x4.shared.b16 {%0,%1,%2,%3}, [%4];"
                                 : "=r"(r0), "=r"(r1), "=r"(r2), "=r"(r3) : "r"(addr));
                    b[p * 2][0] = r0;  b[p * 2][1] = r1;
                    b[p * 2 + 1][0] = r2;  b[p * 2 + 1][1] = r3;
                }
                #pragma unroll
                for (int mi = 0; mi < 4; mi++)
                    #pragma unroll
                    for (int ni = 0; ni < 4; ni++) {
                        asm volatile(
                            "mma.sync.aligned.m16n8k16.row.col.f32.bf16.bf16.f32 "
                            "{%0,%1,%2,%3}, {%4,%5,%6,%7}, {%8,%9}, {%0,%1,%2,%3};"
                            : "+f"(acc[mi][ni][0]), "+f"(acc[mi][ni][1]),
                              "+f"(acc[mi][ni][2]), "+f"(acc[mi][ni][3])
                            : "r"(a[mi][0]), "r"(a[mi][1]), "r"(a[mi][2]), "r"(a[mi][3]),
                              "r"(b[ni][0]), "r"(b[ni][1]));
                    }
            }
        }

        #pragma unroll
        for (int mi = 0; mi < 4; mi++)
            #pragma unroll
            for (int ni = 0; ni < 4; ni++)
                #pragma unroll
                for (int rr = 0; rr < 2; rr++) {
                    int row = tp + wm * 64 + mi * 16 + (lane >> 2) + rr * 8;
                    int col = tq + wn * 32 + ni * 8 + (lane & 3) * 2;
                    float2 v = make_float2(acc[mi][ni][rr * 2], acc[mi][ni][rr * 2 + 1]);
                    *(float2*)(out + row * 256 + col) = v;
                }
    }
}

// =======================================================================
// Kernel E: hsic reduce (128 blocks) + last-block combine
// =======================================================================
__global__ void reduce_combine_kernel(float* __restrict__ out) {
    int tid = threadIdx.x;
    int bx = blockIdx.x;
    const float invB = 1.f / (float)BN;
    __shared__ float red[256];

    float local = 0.f;
    #pragma unroll
    for (int rep = 0; rep < 2; rep++) {
        int e = bx * 512 + rep * 256 + tid;
        int p = e >> 8, q = e & 255;
        float s0 = 0.f, s1 = 0.f;
        #pragma unroll
        for (int s = 0; s < 16; s++) {
            s0 += g_Ms[0][s][e];
            s1 += g_Ms[1][s][e];
        }
        float m0 = s0 - g_colsum[0][p] * g_colsum[1][q] * invB;
        float m1 = s1 - g_colsum[2][p] * g_colsum[3][q] * invB;
        local += m0 * m0 + m1 * m1;
    }
    red[tid] = local;
    __syncthreads();
    for (int s = 128; s; s >>= 1) { if (tid < s) red[tid] += red[tid + s]; __syncthreads(); }
    if (tid == 0) g_hpart[bx] = red[0];
    __threadfence();

    __shared__ int is_last;
    if (tid == 0) {
        int t = atomicAdd(&g_ticket, 1);
        is_last = (t == 127) ? 1 : 0;
    }
    __syncthreads();
    if (!is_last) return;
    if (tid == 0) g_ticket = 0;     // self-reset for next replay
    __threadfence();

    // ---- last block: final combine ----
    __shared__ float cntS[16];
    if (tid < 16) cntS[tid] = 0.f;
    __syncthreads();
    for (int r = tid; r < BN; r += 256) {
        int c = g_cls[r];
        if (c >= 0) atomicAdd(&cntS[c], 1.f);
    }

    float hp = (tid < 128) ? g_hpart[tid] : 0.f;
    float rp = 0.f;
    rp += g_rpart[tid];
    rp += g_rpart[tid + 256];
    red[tid] = hp;
    __syncthreads();
    for (int s = 128; s; s >>= 1) { if (tid < s) red[tid] += red[tid + s]; __syncthreads(); }
    float hsic_frob = red[0];
    __syncthreads();
    red[tid] = rp;
    __syncthreads();
    for (int s = 128; s; s >>= 1) { if (tid < s) red[tid] += red[tid + s]; __syncthreads(); }
    float recon_sum = red[0];
    __syncthreads();

    if (tid == 0) {
        float hsic_sum = hsic_frob / (4095.f * 4095.f);

        float ls[5];
        for (int t = 0; t < 5; t++) {
            float s = 0.f;
            for (int k = 0; k < 16; k++) s += g_lpart[t][k];
            ls[t] = s;
        }
        float msum = 0.f;
        for (int k = 0; k < 16; k++) msum += cntS[k];
        // note: masksum == sum of class counts only because cls>=0 iff masked-in
        msum = fmaxf(msum, 1.f);

        float mmd[2];
        for (int s = 0; s < 2; s++) {
            float loss = 0.f, count = 0.f;
            for (int lab = 0; lab < 4; lab++)
                for (int d1 = 0; d1 < 4; d1++) {
                    int a = lab * 4 + d1;
                    float n1 = cntS[a];
                    for (int d2 = d1 + 1; d2 < 4; d2++) {
                        int b = lab * 4 + d2;
                        float n2 = cntS[b];
                        if (n1 > 1.f && n2 > 1.f) {
                            float ga = 2.f * g_G[s][a * 16 + a];
                            float gb = 2.f * g_G[s][b * 16 + b];
                            float gab = g_G[s][a * 16 + b] + g_G[s][b * 16 + a];
                            float m1m = fmaxf(n1, 1.f), m2m = fmaxf(n2, 1.f);
                            float term = ga / (m1m * m1m) + gb / (m2m * m2m)
                                       - 2.f * gab / fmaxf(n1 * n2, 1.f);
                            loss += term;
                            count += 1.f;
                        }
                    }
                }
            mmd[s] = loss / fmaxf(count, 1.f);
        }

        float total = 0.4f * ls[0] / msum + 0.3f * ls[1] / msum + 0.3f * ls[2] / msum;
        total += 0.1f * (ls[3] / msum + ls[4] / msum + mmd[0] + mmd[1]);
        total += 0.1f * hsic_sum;
        total += recon_sum / (float)(BN * HN);
        out[0] = total;
    }
}

// ---------------- launch ----------------
extern "C" void kernel_launch(void* const* d_in, const int* in_sizes, int n_in,
                              void* d_out, int out_size) {
    (void)in_sizes; (void)n_in; (void)out_size;
    const float* logits1 = (const float*)d_in[0];
    const int*   labels1 = (const int*)d_in[1];
    const float* logits2 = (const float*)d_in[2];
    const int*   labels2 = (const int*)d_in[3];
    const float* logits3 = (const float*)d_in[4];
    const int*   labels3 = (const int*)d_in[5];
    const float* c_v  = (const float*)d_in[6];
    const float* s_v  = (const float*)d_in[7];
    const float* c_t  = (const float*)d_in[8];
    const float* s_t  = (const float*)d_in[9];
    const float* v_sv = (const float*)d_in[10];
    const float* v_st = (const float*)d_in[11];
    const int*   dom  = (const int*)d_in[12];
    const unsigned char* mask = (const unsigned char*)d_in[13];
    const float* hir = (const float*)d_in[14];
    const float* hio = (const float*)d_in[15];
    const float* htr = (const float*)d_in[16];
    const float* hto = (const float*)d_in[17];

    prep_kernel<<<dim3(512, 6), 256>>>(c_v, c_t, s_v, s_t, labels1, dom, mask,
                                       logits1, labels1, logits2, labels2, logits3, labels3,
                                       v_sv, v_st, hir, hio, htr, hto);
    transposeN_kernel<<<dim3(64, 4, 4), 256>>>(c_v, s_v, c_t, s_t);
    gram_hsic_kernel<<<1184, 256>>>();
    reduce_combine_kernel<<<128, 256>>>((float*)d_out);
}